// round 16
// baseline (speedup 1.0000x reference)
#include <cuda_runtime.h>
#include <cuda_bf16.h>
#include <math.h>
#include <stdint.h>

// ---------------------------------------------------------------------------
// Shapes (fixed): N=2, C=128, H=W=64 -> TOK=8192 tokens; heads=4, d=32, k=7,
// hid=512, L=2. Activations NHWC. GEMMs on tensor cores via mma.sync bf16
// with 3-term split (Ah*Bh + Ah*Bl + Al*Bh), fp32 accumulate.
// (tcgen05 is unavailable: harness PTX targets sm_103 without the 'a' suffix.)
// ---------------------------------------------------------------------------

#define TOK      8192
#define CH       128
#define HW       4096
#define ELEMS    1048576   /* TOK*CH */
#define HID      512
#define K_CONV   1152      /* 9*128 */

typedef __nv_bfloat16 bf16;

// ------------------------- scratch (static device) -------------------------
__device__ float g_res [ELEMS];
__device__ float g_qkv [TOK * 384];
__device__ float g_t   [ELEMS];
__device__ float g_h   [TOK * HID];
__device__ float g_conv[ELEMS];
__device__ float g_y1  [TOK * 32];
__device__ float g_y2  [ELEMS];
__device__ float g_part[128];
__device__ float g_stat[4];
__device__ float g_pp  [64 * CH];
__device__ float g_p   [2 * CH];
__device__ float g_s   [2 * CH];

// bf16 hi/lo activation pairs
__device__ bf16 g_xg_h [ELEMS],     g_xg_l [ELEMS];
__device__ bf16 g_a_h  [ELEMS],     g_a_l  [ELEMS];
__device__ bf16 g_ln_h [ELEMS],     g_ln_l [ELEMS];
__device__ bf16 g_hh_h [TOK * HID], g_hh_l [TOK * HID];
__device__ bf16 g_res_h[ELEMS],     g_res_l[ELEMS];

// bf16 hi/lo weights
__device__ bf16 g_qw_h [2 * 384 * 128], g_qw_l [2 * 384 * 128];
__device__ bf16 g_pw_h [2 * 128 * 128], g_pw_l [2 * 128 * 128];
__device__ bf16 g_f1_h [2 * 512 * 128], g_f1_l [2 * 512 * 128];
__device__ bf16 g_f2_h [2 * 128 * 512], g_f2_l [2 * 128 * 512];
__device__ bf16 g_wp_h [CH * K_CONV],   g_wp_l [CH * K_CONV];

// ------------------------------ helpers ------------------------------------
__device__ __forceinline__ float warp_sum(float v) {
    v += __shfl_xor_sync(0xffffffffu, v, 16);
    v += __shfl_xor_sync(0xffffffffu, v, 8);
    v += __shfl_xor_sync(0xffffffffu, v, 4);
    v += __shfl_xor_sync(0xffffffffu, v, 2);
    v += __shfl_xor_sync(0xffffffffu, v, 1);
    return v;
}

__device__ __forceinline__ float gelu_exact(float x) {
    return 0.5f * x * (1.0f + erff(x * 0.70710678118654752440f));
}

__device__ __forceinline__ void splitf(float v, unsigned short& h, unsigned short& l) {
    bf16 hh = __float2bfloat16(v);
    h = __bfloat16_as_ushort(hh);
    l = __bfloat16_as_ushort(__float2bfloat16(v - __bfloat162float(hh)));
}

__device__ __forceinline__ void split4(float a, float b, float c, float d,
                                       uint2& hi, uint2& lo) {
    unsigned short h0,h1,h2,h3,l0,l1,l2,l3;
    splitf(a,h0,l0); splitf(b,h1,l1); splitf(c,h2,l2); splitf(d,h3,l3);
    hi.x = (unsigned)h0 | ((unsigned)h1 << 16);
    hi.y = (unsigned)h2 | ((unsigned)h3 << 16);
    lo.x = (unsigned)l0 | ((unsigned)l1 << 16);
    lo.y = (unsigned)l2 | ((unsigned)l3 << 16);
}

__device__ __forceinline__ void split2(float a, float b, unsigned& hi, unsigned& lo) {
    unsigned short h0,h1,l0,l1;
    splitf(a,h0,l0); splitf(b,h1,l1);
    hi = (unsigned)h0 | ((unsigned)h1 << 16);
    lo = (unsigned)l0 | ((unsigned)l1 << 16);
}

__device__ __forceinline__ uint32_t smem_u32(const void* p) {
    uint32_t a;
    asm("{ .reg .u64 t; cvta.to.shared.u64 t, %1; cvt.u32.u64 %0, t; }" : "=r"(a) : "l"(p));
    return a;
}

// ------------------------ mma.sync / ldmatrix helpers ------------------------
__device__ __forceinline__ void ldsm_x4(uint32_t* r, uint32_t addr) {
    asm volatile("ldmatrix.sync.aligned.m8n8.x4.shared.b16 {%0,%1,%2,%3}, [%4];"
        : "=r"(r[0]), "=r"(r[1]), "=r"(r[2]), "=r"(r[3]) : "r"(addr));
}
__device__ __forceinline__ void ldsm_x2(uint32_t* r, uint32_t addr) {
    asm volatile("ldmatrix.sync.aligned.m8n8.x2.shared.b16 {%0,%1}, [%2];"
        : "=r"(r[0]), "=r"(r[1]) : "r"(addr));
}
__device__ __forceinline__ void mma_bf16(float* d, const uint32_t* a, const uint32_t* b) {
    asm volatile("mma.sync.aligned.m16n8k16.row.col.f32.bf16.bf16.f32 "
        "{%0,%1,%2,%3}, {%4,%5,%6,%7}, {%8,%9}, {%0,%1,%2,%3};"
        : "+f"(d[0]), "+f"(d[1]), "+f"(d[2]), "+f"(d[3])
        : "r"(a[0]), "r"(a[1]), "r"(a[2]), "r"(a[3]), "r"(b[0]), "r"(b[1]));
}

// ---------------------------------------------------------------------------
// Tensor-core split-3 GEMM: C[M,N] = (Ah+Al)[M,K] @ (Bh+Bl)[N,K]^T + bias
// Block tile 64x128, 8 warps (warp tile 32x32), K-blocks of 32, double-buffer.
// EPI: 0 none, 1 +R, 2 relu, 3 gelu. CONV: im2col gather for A rows.
// WB: also write bf16 hi/lo split of output.
// smem per buffer: Ah[64][40] Al[64][40] Bh[128][40] Bl[128][40] bf16
//   offsets (bytes): 0, 5120, 10240, 20480; buffer stride 30720; total 61440.
// ---------------------------------------------------------------------------
#define TG_SMEM 61440

template <int EPI, bool CONV, bool WB>
__global__ void __launch_bounds__(256)
tgemm(const bf16* __restrict__ Ah, const bf16* __restrict__ Al,
      const bf16* __restrict__ Bh, const bf16* __restrict__ Bl,
      const float* __restrict__ bias, const float* __restrict__ R,
      float* __restrict__ Cf, bf16* __restrict__ Ch, bf16* __restrict__ Cl,
      int N, int K) {
    extern __shared__ char smem[];
    const uint32_t sb = smem_u32(smem);
    const int tid  = threadIdx.x;
    const int lane = tid & 31;
    const int wid  = tid >> 5;
    const int wm   = wid & 1;       // 2 m-warps
    const int wn   = wid >> 1;      // 4 n-warps
    const int bm   = blockIdx.x * 64;
    const int bn   = blockIdx.y * 128;

    const int arowL = tid >> 2;     // 0..63
    const int c4    = tid & 3;      // 16B chunk within 64B row

    float acc[2][4][4];
#pragma unroll
    for (int i = 0; i < 2; i++)
#pragma unroll
        for (int j = 0; j < 4; j++)
#pragma unroll
            for (int q = 0; q < 4; q++) acc[i][j][q] = 0.f;

    uint4 va_h, va_l, vb_h0, vb_h1, vb_l0, vb_l1;

    auto loadT = [&](int kb) {
        const int k0 = kb * 32;
        if (CONV) {
            const int p9 = kb >> 2;
            const int ky = p9 / 3, kx = p9 - ky * 3;
            const int ci = (kb & 3) * 32 + c4 * 8;
            const int tokm = bm + arowL;
            const int y = ((tokm >> 6) & 63) + ky - 1;
            const int x = (tokm & 63) + kx - 1;
            if ((unsigned)y < 64u && (unsigned)x < 64u) {
                const size_t off = ((size_t)(((tokm >> 12) << 12) + (y << 6) + x) << 7) + ci;
                va_h = *(const uint4*)(Ah + off);
                va_l = *(const uint4*)(Al + off);
            } else {
                va_h = make_uint4(0, 0, 0, 0); va_l = va_h;
            }
        } else {
            const size_t off = (size_t)(bm + arowL) * K + k0 + c4 * 8;
            va_h = *(const uint4*)(Ah + off);
            va_l = *(const uint4*)(Al + off);
        }
        const size_t b0 = (size_t)(bn + arowL) * K + k0 + c4 * 8;
        const size_t b1 = (size_t)(bn + 64 + arowL) * K + k0 + c4 * 8;
        vb_h0 = *(const uint4*)(Bh + b0);
        vb_h1 = *(const uint4*)(Bh + b1);
        vb_l0 = *(const uint4*)(Bl + b0);
        vb_l1 = *(const uint4*)(Bl + b1);
    };

    auto storeT = [&](int s) {
        char* base = smem + s * 30720;
        *(uint4*)(base + arowL * 80 + c4 * 16)                 = va_h;
        *(uint4*)(base + 5120 + arowL * 80 + c4 * 16)          = va_l;
        *(uint4*)(base + 10240 + arowL * 80 + c4 * 16)         = vb_h0;
        *(uint4*)(base + 10240 + (64 + arowL) * 80 + c4 * 16)  = vb_h1;
        *(uint4*)(base + 20480 + arowL * 80 + c4 * 16)         = vb_l0;
        *(uint4*)(base + 20480 + (64 + arowL) * 80 + c4 * 16)  = vb_l1;
    };

    const int nkb = K >> 5;
    const uint32_t aoff = (lane & 15) * 80 + (lane >> 4) * 16;
    const uint32_t boff = (lane & 7) * 80 + ((lane >> 3) & 1) * 16;

    loadT(0);
    for (int kb = 0; kb < nkb; kb++) {
        const int s = kb & 1;
        storeT(s);
        __syncthreads();
        if (kb + 1 < nkb) loadT(kb + 1);
        const uint32_t bufb = sb + s * 30720;
#pragma unroll
        for (int k16 = 0; k16 < 2; k16++) {
            const uint32_t kko = k16 * 32;   // 16 bf16 = 32 bytes
            uint32_t ah2[2][4], al2[2][4], bh2[4][2], bl2[4][2];
#pragma unroll
            for (int mi = 0; mi < 2; mi++) {
                const uint32_t rb = (uint32_t)(wm * 32 + mi * 16) * 80;
                ldsm_x4(ah2[mi], bufb + rb + aoff + kko);
                ldsm_x4(al2[mi], bufb + 5120 + rb + aoff + kko);
            }
#pragma unroll
            for (int ni = 0; ni < 4; ni++) {
                const uint32_t rb = (uint32_t)(wn * 32 + ni * 8) * 80;
                ldsm_x2(bh2[ni], bufb + 10240 + rb + boff + kko);
                ldsm_x2(bl2[ni], bufb + 20480 + rb + boff + kko);
            }
#pragma unroll
            for (int mi = 0; mi < 2; mi++)
#pragma unroll
                for (int ni = 0; ni < 4; ni++) {
                    mma_bf16(acc[mi][ni], ah2[mi], bh2[ni]);
                    mma_bf16(acc[mi][ni], ah2[mi], bl2[ni]);
                    mma_bf16(acc[mi][ni], al2[mi], bh2[ni]);
                }
        }
    }

    // --- epilogue: registers -> global ---
    const int rq = lane >> 2;
    const int cq = (lane & 3) * 2;
#pragma unroll
    for (int mi = 0; mi < 2; mi++) {
        const int mA = bm + wm * 32 + mi * 16 + rq;
#pragma unroll
        for (int ni = 0; ni < 4; ni++) {
            const int n0 = bn + wn * 32 + ni * 8 + cq;
            const float bv0 = bias[n0], bv1 = bias[n0 + 1];
#pragma unroll
            for (int half = 0; half < 2; half++) {
                const int m = mA + half * 8;
                float v0 = acc[mi][ni][half * 2 + 0] + bv0;
                float v1 = acc[mi][ni][half * 2 + 1] + bv1;
                if (EPI == 1) {
                    v0 += R[(size_t)m * N + n0];
                    v1 += R[(size_t)m * N + n0 + 1];
                }
                if (EPI == 2) { v0 = fmaxf(v0, 0.f); v1 = fmaxf(v1, 0.f); }
                if (EPI == 3) { v0 = gelu_exact(v0); v1 = gelu_exact(v1); }
                float2 o; o.x = v0; o.y = v1;
                *(float2*)&Cf[(size_t)m * N + n0] = o;
                if (WB) {
                    unsigned hi, lo;
                    split2(v0, v1, hi, lo);
                    *(unsigned*)(Ch + (size_t)m * N + n0) = hi;
                    *(unsigned*)(Cl + (size_t)m * N + n0) = lo;
                }
            }
        }
    }
}

// ----------------------- NCHW -> NHWC transpose -----------------------------
__global__ void nchw_to_nhwc(const float* __restrict__ x, float* __restrict__ o) {
    int idx = blockIdx.x * blockDim.x + threadIdx.x;
    if (idx >= ELEMS) return;
    int c  = idx & 127;
    int hw = (idx >> 7) & 4095;
    int n  = idx >> 19;
    o[idx] = x[((n * CH + c) << 12) + hw];
}

// ------------------------- weight split kernels -----------------------------
__global__ void wsplit(const float* __restrict__ w, bf16* __restrict__ h,
                       bf16* __restrict__ l, int n) {
    int i = blockIdx.x * 256 + threadIdx.x;
    if (i >= n) return;
    unsigned short hh, ll;
    splitf(w[i], hh, ll);
    h[i] = __ushort_as_bfloat16(hh);
    l[i] = __ushort_as_bfloat16(ll);
}

__global__ void wpack2(const float* __restrict__ bw, bf16* __restrict__ h,
                       bf16* __restrict__ l) {
    int idx = blockIdx.x * 256 + threadIdx.x;
    if (idx >= CH * K_CONV) return;
    int co = idx / K_CONV;
    int r  = idx - co * K_CONV;
    int p9 = r >> 7;
    int ci = r & 127;
    unsigned short hh, ll;
    splitf(bw[co * K_CONV + ci * 9 + p9], hh, ll);
    h[idx] = __ushort_as_bfloat16(hh);
    l[idx] = __ushort_as_bfloat16(ll);
}

// -------------------------- GroupNorm(1, C) ---------------------------------
__global__ void gn_stage1(const float* __restrict__ res, float* __restrict__ part) {
    int b = blockIdx.x;
    const float4* p = (const float4*)(res + (size_t)b * 16384);
    float s = 0.f, s2 = 0.f;
    for (int i = threadIdx.x; i < 4096; i += 256) {
        float4 v = p[i];
        s  += v.x + v.y + v.z + v.w;
        s2 += v.x*v.x + v.y*v.y + v.z*v.z + v.w*v.w;
    }
    __shared__ float sh[8], sh2[8];
    s = warp_sum(s); s2 = warp_sum(s2);
    int wid = threadIdx.x >> 5, lane = threadIdx.x & 31;
    if (lane == 0) { sh[wid] = s; sh2[wid] = s2; }
    __syncthreads();
    if (threadIdx.x == 0) {
        float a = 0.f, a2 = 0.f;
        for (int i = 0; i < 8; i++) { a += sh[i]; a2 += sh2[i]; }
        part[b * 2] = a; part[b * 2 + 1] = a2;
    }
}

__global__ void gn_stage2(const float* __restrict__ part, float* __restrict__ stats) {
    int n = blockIdx.x, i = threadIdx.x;
    float s  = part[(n * 32 + i) * 2];
    float s2 = part[(n * 32 + i) * 2 + 1];
    s = warp_sum(s); s2 = warp_sum(s2);
    if (i == 0) {
        float mu  = s  * (1.f / 524288.f);
        float var = s2 * (1.f / 524288.f) - mu * mu;
        stats[n * 2]     = mu;
        stats[n * 2 + 1] = rsqrtf(var + 1e-5f);
    }
}

__global__ void gn_apply2(const float* __restrict__ res, const float* __restrict__ stats,
                          const float* __restrict__ g, const float* __restrict__ b,
                          bf16* __restrict__ xh, bf16* __restrict__ xl) {
    int i4 = blockIdx.x * 256 + threadIdx.x;
    if (i4 >= ELEMS / 4) return;
    int c4 = i4 & 31;
    int n  = i4 >> 17;
    float mu = stats[n * 2], rs = stats[n * 2 + 1];
    float4 v  = ((const float4*)res)[i4];
    float4 gg = ((const float4*)g)[c4];
    float4 bb = ((const float4*)b)[c4];
    uint2 hi, lo;
    split4((v.x - mu) * rs * gg.x + bb.x, (v.y - mu) * rs * gg.y + bb.y,
           (v.z - mu) * rs * gg.z + bb.z, (v.w - mu) * rs * gg.w + bb.w, hi, lo);
    ((uint2*)xh)[i4] = hi;
    ((uint2*)xl)[i4] = lo;
}

// ----------------------- 7x7 neighborhood attention -------------------------
__global__ void __launch_bounds__(256)
na_attn2(const float* __restrict__ qkv, const float* __restrict__ rpb,
         bf16* __restrict__ oh, bf16* __restrict__ ol) {
    int tok  = (blockIdx.x * 256 + threadIdx.x) >> 5;
    int lane = threadIdx.x & 31;
    int head = lane >> 3;
    int dc   = lane & 7;
    int n = tok >> 12, h = (tok >> 6) & 63, w = tok & 63;
    int i0 = min(max(h - 3, 0), 57);
    int j0 = min(max(w - 3, 0), 57);

    const float* base = qkv + ((size_t)(n << 12)) * 384;
    const int co = head * 32 + dc * 4;

    float4 q = *(const float4*)(qkv + (size_t)tok * 384 + co);
    const float sc = 0.17677669529663687f;
    q.x *= sc; q.y *= sc; q.z *= sc; q.w *= sc;

    const float* rp = rpb + head * 169 + (i0 - h + 6) * 13 + (j0 - w + 6);

    float s[7] = {-1e30f, -1e30f, -1e30f, -1e30f, -1e30f, -1e30f, -1e30f};
    float m = -1e30f;
#pragma unroll
    for (int jj = 0; jj < 49; jj++) {
        const int r = jj / 7, cd = jj % 7;
        const int kt = ((i0 + r) << 6) + (j0 + cd);
        float4 kv = *(const float4*)(base + (size_t)kt * 384 + 128 + co);
        float p = q.x * kv.x + q.y * kv.y + q.z * kv.z + q.w * kv.w;
        p += __shfl_xor_sync(0xffffffffu, p, 4);
        p += __shfl_xor_sync(0xffffffffu, p, 2);
        p += __shfl_xor_sync(0xffffffffu, p, 1);
        p += rp[r * 13 + cd];
        m = fmaxf(m, p);
        if (dc == (jj & 7)) s[jj >> 3] = p;
    }

    float e[7];
    float z = 0.f;
#pragma unroll
    for (int i = 0; i < 7; i++) { e[i] = __expf(s[i] - m); z += e[i]; }
    z += __shfl_xor_sync(0xffffffffu, z, 4);
    z += __shfl_xor_sync(0xffffffffu, z, 2);
    z += __shfl_xor_sync(0xffffffffu, z, 1);
    const float inv = 1.f / z;

    float4 acc = make_float4(0.f, 0.f, 0.f, 0.f);
#pragma unroll
    for (int jj = 0; jj < 49; jj++) {
        const int r = jj / 7, cd = jj % 7;
        const int kt = ((i0 + r) << 6) + (j0 + cd);
        float wgt = __shfl_sync(0xffffffffu, e[jj >> 3], (lane & 24) | (jj & 7));
        float4 v = *(const float4*)(base + (size_t)kt * 384 + 256 + co);
        acc.x += wgt * v.x; acc.y += wgt * v.y;
        acc.z += wgt * v.z; acc.w += wgt * v.w;
    }
    uint2 hi, lo;
    split4(acc.x * inv, acc.y * inv, acc.z * inv, acc.w * inv, hi, lo);
    ((uint2*)oh)[tok * 32 + (co >> 2)] = hi;
    ((uint2*)ol)[tok * 32 + (co >> 2)] = lo;
}

// ------------------------------ LayerNorm -----------------------------------
__global__ void ln2(const float* __restrict__ t, const float* __restrict__ g,
                    const float* __restrict__ b, bf16* __restrict__ oh,
                    bf16* __restrict__ ol) {
    int wid  = (blockIdx.x * 256 + threadIdx.x) >> 5;
    int lane = threadIdx.x & 31;
    const float4* p = (const float4*)(t + (size_t)wid * CH);
    float4 v = p[lane];
    float s  = v.x + v.y + v.z + v.w;
    float s2 = v.x*v.x + v.y*v.y + v.z*v.z + v.w*v.w;
    s = warp_sum(s); s2 = warp_sum(s2);
    float mu = s * (1.f / 128.f);
    float rs = rsqrtf(s2 * (1.f / 128.f) - mu * mu + 1e-5f);
    float4 gg = ((const float4*)g)[lane];
    float4 bb = ((const float4*)b)[lane];
    uint2 hi, lo;
    split4((v.x - mu) * rs * gg.x + bb.x, (v.y - mu) * rs * gg.y + bb.y,
           (v.z - mu) * rs * gg.z + bb.z, (v.w - mu) * rs * gg.w + bb.w, hi, lo);
    ((uint2*)oh)[wid * 32 + lane] = hi;
    ((uint2*)ol)[wid * 32 + lane] = lo;
}

// ------------------------- fp32 SGEMM (tiny tail) ---------------------------
template <int EPI>
__global__ void __launch_bounds__(256)
sgemm2(const float* __restrict__ A, const float* __restrict__ B,
       const float* __restrict__ bias, const float* __restrict__ R,
       float* __restrict__ C, int N, int K) {
    __shared__ float As[2][16][64];
    __shared__ float Bs[2][16][128];
    const int bm  = blockIdx.x * 64;
    const int bn  = blockIdx.y * 128;
    const int tid = threadIdx.x;
    const int ar  = tid >> 2;
    const int kc  = (tid & 3) * 4;
    const int ty  = tid >> 4;
    const int tx  = tid & 15;

    float acc[4][8];
#pragma unroll
    for (int i = 0; i < 4; i++)
#pragma unroll
        for (int j = 0; j < 8; j++) acc[i][j] = 0.f;

    const float* Ap  = A + (size_t)(bm + ar) * K + kc;
    const float* Bp0 = B + (size_t)(bn + ar) * K + kc;
    const float* Bp1 = B + (size_t)(bn + ar + 64) * K + kc;
    const bool bv0 = (bn + ar) < N;
    const bool bv1 = (bn + ar + 64) < N;

    const float4 zero4 = make_float4(0.f, 0.f, 0.f, 0.f);
    float4 ra  = *(const float4*)(Ap);
    float4 rb0 = bv0 ? *(const float4*)(Bp0) : zero4;
    float4 rb1 = bv1 ? *(const float4*)(Bp1) : zero4;

    const int nt = K / 16;
    for (int it = 0; it < nt; it++) {
        const int s = it & 1;
        As[s][kc+0][ar] = ra.x;  As[s][kc+1][ar] = ra.y;
        As[s][kc+2][ar] = ra.z;  As[s][kc+3][ar] = ra.w;
        Bs[s][kc+0][ar] = rb0.x; Bs[s][kc+1][ar] = rb0.y;
        Bs[s][kc+2][ar] = rb0.z; Bs[s][kc+3][ar] = rb0.w;
        Bs[s][kc+0][ar+64] = rb1.x; Bs[s][kc+1][ar+64] = rb1.y;
        Bs[s][kc+2][ar+64] = rb1.z; Bs[s][kc+3][ar+64] = rb1.w;
        __syncthreads();
        if (it + 1 < nt) {
            int k0 = (it + 1) * 16;
            ra  = *(const float4*)(Ap + k0);
            rb0 = bv0 ? *(const float4*)(Bp0 + k0) : zero4;
            rb1 = bv1 ? *(const float4*)(Bp1 + k0) : zero4;
        }
#pragma unroll
        for (int kk = 0; kk < 16; kk++) {
            float4 a  = *(const float4*)&As[s][kk][ty * 4];
            float4 b0 = *(const float4*)&Bs[s][kk][tx * 8];
            float4 b1 = *(const float4*)&Bs[s][kk][tx * 8 + 4];
            float av[4] = {a.x, a.y, a.z, a.w};
            float bv[8] = {b0.x, b0.y, b0.z, b0.w, b1.x, b1.y, b1.z, b1.w};
#pragma unroll
            for (int i = 0; i < 4; i++)
#pragma unroll
                for (int j = 0; j < 8; j++) acc[i][j] += av[i] * bv[j];
        }
    }
    __syncthreads();

#pragma unroll
    for (int i = 0; i < 4; i++) {
        int m = bm + ty * 4 + i;
#pragma unroll
        for (int j = 0; j < 8; j++) {
            int n = bn + tx * 8 + j;
            if (n < N) {
                float v = acc[i][j] + bias[n];
                if (EPI == 1) v += R[(size_t)m * N + n];
                if (EPI == 2) v = fmaxf(v, 0.f);
                C[(size_t)m * N + n] = v;
            }
        }
    }
}

// ---------------------------- tail: pool + CA -------------------------------
__global__ void pool1(const float* __restrict__ y2, float* __restrict__ pp) {
    int b = blockIdx.x;
    int c = threadIdx.x;
    const float* p = y2 + (size_t)b * 128 * CH;
    float s = 0.f;
    for (int t = 0; t < 128; t++) s += p[t * CH + c];
    pp[b * CH + c] = s;
}

__global__ void pool2(const float* __restrict__ pp, float* __restrict__ p) {
    int n = blockIdx.x, c = threadIdx.x;
    float s = 0.f;
    for (int b = 0; b < 32; b++) s += pp[(n * 32 + b) * CH + c];
    p[n * CH + c] = s * (1.f / 4096.f);
}

__global__ void ca_kernel(const float* __restrict__ p,
                          const float* __restrict__ w1, const float* __restrict__ b1,
                          const float* __restrict__ w2, const float* __restrict__ b2,
                          float* __restrict__ s) {
    int n = blockIdx.x, c = threadIdx.x;
    __shared__ float sp[128], sh[7];
    sp[c] = p[n * CH + c];
    __syncthreads();
    if (c < 7) {
        float a = b1[c];
        for (int i = 0; i < 128; i++) a += w1[c * 128 + i] * sp[i];
        sh[c] = fmaxf(a, 0.f);
    }
    __syncthreads();
    float a = b2[c];
    for (int j = 0; j < 7; j++) a += w2[c * 7 + j] * sh[j];
    s[n * CH + c] = 1.f / (1.f + __expf(-a));
}

__global__ void final_k(const float* __restrict__ y2, const float* __restrict__ s,
                        const float* __restrict__ x, float* __restrict__ out) {
    int idx = blockIdx.x * blockDim.x + threadIdx.x;   // NCHW index
    if (idx >= ELEMS) return;
    int hw = idx & 4095;
    int c  = (idx >> 12) & 127;
    int n  = idx >> 19;
    out[idx] = y2[(((size_t)(n << 12) + hw) << 7) + c] * s[n * CH + c] + x[idx];
}

// ------------------------------- launcher -----------------------------------
template <typename T>
static T* symf(const void* s) {
    void* p = nullptr;
    cudaGetSymbolAddress(&p, s);
    return (T*)p;
}

extern "C" void kernel_launch(void* const* d_in, const int* in_sizes, int n_in,
                              void* d_out, int out_size) {
    const float* x      = (const float*)d_in[0];
    const float* gn_g   = (const float*)d_in[1];
    const float* gn_b   = (const float*)d_in[2];
    const float* qkv_w  = (const float*)d_in[3];
    const float* qkv_b  = (const float*)d_in[4];
    const float* proj_w = (const float*)d_in[5];
    const float* proj_b = (const float*)d_in[6];
    const float* rpb    = (const float*)d_in[7];
    const float* ln_g   = (const float*)d_in[8];
    const float* ln_b   = (const float*)d_in[9];
    const float* fc1_w  = (const float*)d_in[10];
    const float* fc1_b  = (const float*)d_in[11];
    const float* fc2_w  = (const float*)d_in[12];
    const float* fc2_b  = (const float*)d_in[13];
    const float* bconv_w= (const float*)d_in[14];
    const float* bconv_b= (const float*)d_in[15];
    const float* c1_w   = (const float*)d_in[16];
    const float* c1_b   = (const float*)d_in[17];
    const float* c2_w   = (const float*)d_in[18];
    const float* c2_b   = (const float*)d_in[19];
    const float* ca1_w  = (const float*)d_in[20];
    const float* ca1_b  = (const float*)d_in[21];
    const float* ca2_w  = (const float*)d_in[22];
    const float* ca2_b  = (const float*)d_in[23];

    float* res  = symf<float>(g_res);
    float* qkv  = symf<float>(g_qkv);
    float* t    = symf<float>(g_t);
    float* hbuf = symf<float>(g_h);
    float* conv = symf<float>(g_conv);
    float* y1   = symf<float>(g_y1);
    float* y2   = symf<float>(g_y2);
    float* part = symf<float>(g_part);
    float* stat = symf<float>(g_stat);
    float* pp   = symf<float>(g_pp);
    float* p    = symf<float>(g_p);
    float* s    = symf<float>(g_s);

    bf16* xg_h = symf<bf16>(g_xg_h);  bf16* xg_l = symf<bf16>(g_xg_l);
    bf16* a_h  = symf<bf16>(g_a_h);   bf16* a_l  = symf<bf16>(g_a_l);
    bf16* ln_h = symf<bf16>(g_ln_h);  bf16* ln_l = symf<bf16>(g_ln_l);
    bf16* hh_h = symf<bf16>(g_hh_h);  bf16* hh_l = symf<bf16>(g_hh_l);
    bf16* res_h= symf<bf16>(g_res_h); bf16* res_l= symf<bf16>(g_res_l);
    bf16* qw_h = symf<bf16>(g_qw_h);  bf16* qw_l = symf<bf16>(g_qw_l);
    bf16* pw_h = symf<bf16>(g_pw_h);  bf16* pw_l = symf<bf16>(g_pw_l);
    bf16* f1_h = symf<bf16>(g_f1_h);  bf16* f1_l = symf<bf16>(g_f1_l);
    bf16* f2_h = symf<bf16>(g_f2_h);  bf16* f2_l = symf<bf16>(g_f2_l);
    bf16* wp_h = symf<bf16>(g_wp_h);  bf16* wp_l = symf<bf16>(g_wp_l);

    cudaFuncSetAttribute(tgemm<0,false,false>, cudaFuncAttributeMaxDynamicSharedMemorySize, TG_SMEM);
    cudaFuncSetAttribute(tgemm<1,false,false>, cudaFuncAttributeMaxDynamicSharedMemorySize, TG_SMEM);
    cudaFuncSetAttribute(tgemm<3,false,true >, cudaFuncAttributeMaxDynamicSharedMemorySize, TG_SMEM);
    cudaFuncSetAttribute(tgemm<1,false,true >, cudaFuncAttributeMaxDynamicSharedMemorySize, TG_SMEM);
    cudaFuncSetAttribute(tgemm<0,true ,false>, cudaFuncAttributeMaxDynamicSharedMemorySize, TG_SMEM);

    nchw_to_nhwc<<<ELEMS / 256, 256>>>(x, res);

    wsplit<<<(2*384*128 + 255) / 256, 256>>>(qkv_w,  qw_h, qw_l, 2*384*128);
    wsplit<<<(2*128*128 + 255) / 256, 256>>>(proj_w, pw_h, pw_l, 2*128*128);
    wsplit<<<(2*512*128 + 255) / 256, 256>>>(fc1_w,  f1_h, f1_l, 2*512*128);
    wsplit<<<(2*128*512 + 255) / 256, 256>>>(fc2_w,  f2_h, f2_l, 2*128*512);
    wpack2<<<(CH*K_CONV + 255) / 256, 256>>>(bconv_w, wp_h, wp_l);

    for (int l = 0; l < 2; l++) {
        gn_stage1<<<64, 256>>>(res, part);
        gn_stage2<<<2, 32>>>(part, stat);
        gn_apply2<<<ELEMS / 4 / 256, 256>>>(res, stat, gn_g + l*128, gn_b + l*128, xg_h, xg_l);

        tgemm<0,false,false><<<dim3(128, 3), 256, TG_SMEM>>>(
            xg_h, xg_l, qw_h + l*49152, qw_l + l*49152,
            qkv_b + l*384, nullptr, qkv, nullptr, nullptr, 384, 128);

        na_attn2<<<1024, 256>>>(qkv, rpb + l*4*169, a_h, a_l);

        tgemm<1,false,false><<<dim3(128, 1), 256, TG_SMEM>>>(
            a_h, a_l, pw_h + l*16384, pw_l + l*16384,
            proj_b + l*128, res, t, nullptr, nullptr, 128, 128);

        ln2<<<1024, 256>>>(t, ln_g + l*128, ln_b + l*128, ln_h, ln_l);

        tgemm<3,false,true><<<dim3(128, 4), 256, TG_SMEM>>>(
            ln_h, ln_l, f1_h + l*65536, f1_l + l*65536,
            fc1_b + l*512, nullptr, hbuf, hh_h, hh_l, 512, 128);

        tgemm<1,false,true><<<dim3(128, 1), 256, TG_SMEM>>>(
            hh_h, hh_l, f2_h + l*65536, f2_l + l*65536,
            fc2_b + l*128, t, res, res_h, res_l, 128, 512);
    }

    tgemm<0,true,false><<<dim3(128, 1), 256, TG_SMEM>>>(
        res_h, res_l, wp_h, wp_l, bconv_b, nullptr, conv, nullptr, nullptr, 128, K_CONV);

    sgemm2<2><<<dim3(128, 1), 256>>>(conv, c1_w, c1_b, nullptr, y1, 32, 128);
    sgemm2<0><<<dim3(128, 1), 256>>>(y1, c2_w, c2_b, nullptr, y2, 128, 32);

    pool1<<<64, 128>>>(y2, pp);
    pool2<<<2, 128>>>(pp, p);
    ca_kernel<<<2, 128>>>(p, ca1_w, ca1_b, ca2_w, ca2_b, s);

    final_k<<<ELEMS / 256, 256>>>(y2, s, x, (float*)d_out);
}

// round 17
// speedup vs baseline: 1.0715x; 1.0715x over previous
#include <cuda_runtime.h>
#include <cuda_bf16.h>
#include <math.h>
#include <stdint.h>

// ---------------------------------------------------------------------------
// N=2, C=128, H=W=64 -> TOK=8192; heads=4, d=32, k=7, hid=512, L=2. NHWC.
// GEMMs: mma.sync bf16 split-3 (Ah*Bh + Ah*Bl + Al*Bh), fp32 accum.
// This round: fuse GN-apply into qkv A-loader, LN into proj epilogue,
// GN stats into transpose/fc2 epilogues, merge weight splits, fused tail.
// ---------------------------------------------------------------------------

#define TOK      8192
#define CH       128
#define HW       4096
#define ELEMS    1048576
#define HID      512
#define K_CONV   1152

typedef __nv_bfloat16 bf16;

// ------------------------- scratch (static device) -------------------------
__device__ float g_res [ELEMS];
__device__ float g_qkv [TOK * 384];
__device__ float g_t   [ELEMS];
__device__ float g_conv[ELEMS];
__device__ float g_y2  [ELEMS];
__device__ float g_part[2048];
__device__ float g_stat[4];
__device__ float g_pp  [128 * CH];
__device__ float g_p   [2 * CH];
__device__ float g_s   [2 * CH];

__device__ bf16 g_a_h  [ELEMS],     g_a_l  [ELEMS];
__device__ bf16 g_ln_h [ELEMS],     g_ln_l [ELEMS];
__device__ bf16 g_hh_h [TOK * HID], g_hh_l [TOK * HID];
__device__ bf16 g_res_h[ELEMS],     g_res_l[ELEMS];

__device__ bf16 g_qw_h [2 * 384 * 128], g_qw_l [2 * 384 * 128];
__device__ bf16 g_pw_h [2 * 128 * 128], g_pw_l [2 * 128 * 128];
__device__ bf16 g_f1_h [2 * 512 * 128], g_f1_l [2 * 512 * 128];
__device__ bf16 g_f2_h [2 * 128 * 512], g_f2_l [2 * 128 * 512];
__device__ bf16 g_wp_h [CH * K_CONV],   g_wp_l [CH * K_CONV];

// ------------------------------ helpers ------------------------------------
__device__ __forceinline__ float warp_sum(float v) {
    v += __shfl_xor_sync(0xffffffffu, v, 16);
    v += __shfl_xor_sync(0xffffffffu, v, 8);
    v += __shfl_xor_sync(0xffffffffu, v, 4);
    v += __shfl_xor_sync(0xffffffffu, v, 2);
    v += __shfl_xor_sync(0xffffffffu, v, 1);
    return v;
}

__device__ __forceinline__ float gelu_exact(float x) {
    return 0.5f * x * (1.0f + erff(x * 0.70710678118654752440f));
}

__device__ __forceinline__ void splitf(float v, unsigned short& h, unsigned short& l) {
    bf16 hh = __float2bfloat16(v);
    h = __bfloat16_as_ushort(hh);
    l = __bfloat16_as_ushort(__float2bfloat16(v - __bfloat162float(hh)));
}

__device__ __forceinline__ void split4(float a, float b, float c, float d,
                                       uint2& hi, uint2& lo) {
    unsigned short h0,h1,h2,h3,l0,l1,l2,l3;
    splitf(a,h0,l0); splitf(b,h1,l1); splitf(c,h2,l2); splitf(d,h3,l3);
    hi.x = (unsigned)h0 | ((unsigned)h1 << 16);
    hi.y = (unsigned)h2 | ((unsigned)h3 << 16);
    lo.x = (unsigned)l0 | ((unsigned)l1 << 16);
    lo.y = (unsigned)l2 | ((unsigned)l3 << 16);
}

__device__ __forceinline__ void split2(float a, float b, unsigned& hi, unsigned& lo) {
    unsigned short h0,h1,l0,l1;
    splitf(a,h0,l0); splitf(b,h1,l1);
    hi = (unsigned)h0 | ((unsigned)h1 << 16);
    lo = (unsigned)l0 | ((unsigned)l1 << 16);
}

__device__ __forceinline__ uint32_t smem_u32(const void* p) {
    uint32_t a;
    asm("{ .reg .u64 t; cvta.to.shared.u64 t, %1; cvt.u32.u64 %0, t; }" : "=r"(a) : "l"(p));
    return a;
}

__device__ __forceinline__ void ldsm_x4(uint32_t* r, uint32_t addr) {
    asm volatile("ldmatrix.sync.aligned.m8n8.x4.shared.b16 {%0,%1,%2,%3}, [%4];"
        : "=r"(r[0]), "=r"(r[1]), "=r"(r[2]), "=r"(r[3]) : "r"(addr));
}
__device__ __forceinline__ void ldsm_x2(uint32_t* r, uint32_t addr) {
    asm volatile("ldmatrix.sync.aligned.m8n8.x2.shared.b16 {%0,%1}, [%2];"
        : "=r"(r[0]), "=r"(r[1]) : "r"(addr));
}
__device__ __forceinline__ void mma_bf16(float* d, const uint32_t* a, const uint32_t* b) {
    asm volatile("mma.sync.aligned.m16n8k16.row.col.f32.bf16.bf16.f32 "
        "{%0,%1,%2,%3}, {%4,%5,%6,%7}, {%8,%9}, {%0,%1,%2,%3};"
        : "+f"(d[0]), "+f"(d[1]), "+f"(d[2]), "+f"(d[3])
        : "r"(a[0]), "r"(a[1]), "r"(a[2]), "r"(a[3]), "r"(b[0]), "r"(b[1]));
}

// ---------------------------------------------------------------------------
// Tensor-core split-3 GEMM, block tile 64x128, 8 warps, K-blocks 32, dbuf.
// EPI: 0 none, 1 +R, 2 relu, 3 gelu.
// CONV: im2col gather for A. WB: write bf16 hi/lo of C. WF: write fp32 C.
// GNA: A = groupnorm(A32) split on the fly (K=128 channels).
// LNE: layernorm epilogue (N==128, full rows per block): Cf=pre-LN fp32,
//      Ch/Cl = LN bf16 splits.  GNP: per-block GN partial sums -> part.
// ---------------------------------------------------------------------------
#define TG_SMEM 61440

template <int EPI, bool CONV, bool WB, bool WF, bool GNA, bool LNE, bool GNP>
__global__ void __launch_bounds__(256)
tgemm(const bf16* __restrict__ Ah, const bf16* __restrict__ Al,
      const float* __restrict__ A32,
      const bf16* __restrict__ Bh, const bf16* __restrict__ Bl,
      const float* __restrict__ bias, const float* __restrict__ R,
      float* __restrict__ Cf, bf16* __restrict__ Ch, bf16* __restrict__ Cl,
      const float* __restrict__ gnst, const float* __restrict__ gng,
      const float* __restrict__ gnb, const float* __restrict__ lng,
      const float* __restrict__ lnb, float* __restrict__ part,
      int N, int K) {
    extern __shared__ char smem[];
    const uint32_t sb = smem_u32(smem);
    const int tid  = threadIdx.x;
    const int lane = tid & 31;
    const int wid  = tid >> 5;
    const int wm   = wid & 1;
    const int wn   = wid >> 1;
    const int bm   = blockIdx.x * 64;
    const int bn   = blockIdx.y * 128;

    const int arowL = tid >> 2;
    const int c4    = tid & 3;

    float gmu = 0.f, grs = 0.f;
    if (GNA) { gmu = gnst[(bm >> 12) * 2]; grs = gnst[(bm >> 12) * 2 + 1]; }

    float acc[2][4][4];
#pragma unroll
    for (int i = 0; i < 2; i++)
#pragma unroll
        for (int j = 0; j < 4; j++)
#pragma unroll
            for (int q = 0; q < 4; q++) acc[i][j][q] = 0.f;

    uint4 va_h, va_l, vb_h0, vb_h1, vb_l0, vb_l1;

    auto loadT = [&](int kb) {
        const int k0 = kb * 32;
        if (CONV) {
            const int p9 = kb >> 2;
            const int ky = p9 / 3, kx = p9 - ky * 3;
            const int ci = (kb & 3) * 32 + c4 * 8;
            const int tokm = bm + arowL;
            const int y = ((tokm >> 6) & 63) + ky - 1;
            const int x = (tokm & 63) + kx - 1;
            if ((unsigned)y < 64u && (unsigned)x < 64u) {
                const size_t off = ((size_t)(((tokm >> 12) << 12) + (y << 6) + x) << 7) + ci;
                va_h = *(const uint4*)(Ah + off);
                va_l = *(const uint4*)(Al + off);
            } else {
                va_h = make_uint4(0, 0, 0, 0); va_l = va_h;
            }
        } else if (GNA) {
            const size_t off = (size_t)(bm + arowL) * K + k0 + c4 * 8;
            float4 v0 = *(const float4*)(A32 + off);
            float4 v1 = *(const float4*)(A32 + off + 4);
            const int ch = k0 + c4 * 8;
            float4 G0 = *(const float4*)(gng + ch);
            float4 G1 = *(const float4*)(gng + ch + 4);
            float4 B0 = *(const float4*)(gnb + ch);
            float4 B1 = *(const float4*)(gnb + ch + 4);
            uint2 h0, l0, h1, l1;
            split4((v0.x - gmu) * grs * G0.x + B0.x, (v0.y - gmu) * grs * G0.y + B0.y,
                   (v0.z - gmu) * grs * G0.z + B0.z, (v0.w - gmu) * grs * G0.w + B0.w, h0, l0);
            split4((v1.x - gmu) * grs * G1.x + B1.x, (v1.y - gmu) * grs * G1.y + B1.y,
                   (v1.z - gmu) * grs * G1.z + B1.z, (v1.w - gmu) * grs * G1.w + B1.w, h1, l1);
            va_h = make_uint4(h0.x, h0.y, h1.x, h1.y);
            va_l = make_uint4(l0.x, l0.y, l1.x, l1.y);
        } else {
            const size_t off = (size_t)(bm + arowL) * K + k0 + c4 * 8;
            va_h = *(const uint4*)(Ah + off);
            va_l = *(const uint4*)(Al + off);
        }
        const size_t b0 = (size_t)(bn + arowL) * K + k0 + c4 * 8;
        const size_t b1 = (size_t)(bn + 64 + arowL) * K + k0 + c4 * 8;
        vb_h0 = *(const uint4*)(Bh + b0);
        vb_h1 = *(const uint4*)(Bh + b1);
        vb_l0 = *(const uint4*)(Bl + b0);
        vb_l1 = *(const uint4*)(Bl + b1);
    };

    auto storeT = [&](int s) {
        char* base = smem + s * 30720;
        *(uint4*)(base + arowL * 80 + c4 * 16)                 = va_h;
        *(uint4*)(base + 5120 + arowL * 80 + c4 * 16)          = va_l;
        *(uint4*)(base + 10240 + arowL * 80 + c4 * 16)         = vb_h0;
        *(uint4*)(base + 10240 + (64 + arowL) * 80 + c4 * 16)  = vb_h1;
        *(uint4*)(base + 20480 + arowL * 80 + c4 * 16)         = vb_l0;
        *(uint4*)(base + 20480 + (64 + arowL) * 80 + c4 * 16)  = vb_l1;
    };

    const int nkb = K >> 5;
    const uint32_t aoff = (lane & 15) * 80 + (lane >> 4) * 16;
    const uint32_t boff = (lane & 7) * 80 + ((lane >> 3) & 1) * 16;

    loadT(0);
    for (int kb = 0; kb < nkb; kb++) {
        const int s = kb & 1;
        storeT(s);
        __syncthreads();
        if (kb + 1 < nkb) loadT(kb + 1);
        const uint32_t bufb = sb + s * 30720;
#pragma unroll
        for (int k16 = 0; k16 < 2; k16++) {
            const uint32_t kko = k16 * 32;
            uint32_t ah2[2][4], al2[2][4], bh2[4][2], bl2[4][2];
#pragma unroll
            for (int mi = 0; mi < 2; mi++) {
                const uint32_t rb = (uint32_t)(wm * 32 + mi * 16) * 80;
                ldsm_x4(ah2[mi], bufb + rb + aoff + kko);
                ldsm_x4(al2[mi], bufb + 5120 + rb + aoff + kko);
            }
#pragma unroll
            for (int ni = 0; ni < 4; ni++) {
                const uint32_t rb = (uint32_t)(wn * 32 + ni * 8) * 80;
                ldsm_x2(bh2[ni], bufb + 10240 + rb + boff + kko);
                ldsm_x2(bl2[ni], bufb + 20480 + rb + boff + kko);
            }
#pragma unroll
            for (int mi = 0; mi < 2; mi++)
#pragma unroll
                for (int ni = 0; ni < 4; ni++) {
                    mma_bf16(acc[mi][ni], ah2[mi], bh2[ni]);
                    mma_bf16(acc[mi][ni], ah2[mi], bl2[ni]);
                    mma_bf16(acc[mi][ni], al2[mi], bh2[ni]);
                }
        }
        if (kb + 1 >= nkb) __syncthreads();  // smem reusable below
    }

    const int rq = lane >> 2;
    const int cq = (lane & 3) * 2;

    if (LNE) {
        // ---- per-row LayerNorm epilogue (N == 128, full rows per block) ----
        float rs0[4], rs2[4];
#pragma unroll
        for (int i = 0; i < 4; i++) { rs0[i] = 0.f; rs2[i] = 0.f; }
#pragma unroll
        for (int mi = 0; mi < 2; mi++)
#pragma unroll
            for (int ni = 0; ni < 4; ni++) {
                const int n0 = bn + wn * 32 + ni * 8 + cq;
                const float bv0 = bias[n0], bv1 = bias[n0 + 1];
#pragma unroll
                for (int half = 0; half < 2; half++) {
                    const int m = bm + wm * 32 + mi * 16 + half * 8 + rq;
                    float v0 = acc[mi][ni][half * 2 + 0] + bv0;
                    float v1 = acc[mi][ni][half * 2 + 1] + bv1;
                    if (EPI == 1) {
                        v0 += R[(size_t)m * N + n0];
                        v1 += R[(size_t)m * N + n0 + 1];
                    }
                    acc[mi][ni][half * 2 + 0] = v0;
                    acc[mi][ni][half * 2 + 1] = v1;
                    const int rr = mi * 2 + half;
                    rs0[rr] += v0 + v1;
                    rs2[rr] += v0 * v0 + v1 * v1;
                }
            }
        float* pr  = (float*)smem;          // [64][17]
        float* pr2 = pr + 64 * 17;
        const int p = wn * 4 + (lane & 3);
#pragma unroll
        for (int mi = 0; mi < 2; mi++)
#pragma unroll
            for (int half = 0; half < 2; half++) {
                const int row = wm * 32 + mi * 16 + half * 8 + rq;
                pr [row * 17 + p] = rs0[mi * 2 + half];
                pr2[row * 17 + p] = rs2[mi * 2 + half];
            }
        __syncthreads();
        if (tid < 64) {
            float s = 0.f, s2 = 0.f;
#pragma unroll
            for (int i = 0; i < 16; i++) { s += pr[tid * 17 + i]; s2 += pr2[tid * 17 + i]; }
            const float mu = s * (1.f / 128.f);
            const float rsg = rsqrtf(s2 * (1.f / 128.f) - mu * mu + 1e-5f);
            pr [tid * 17 + 16] = mu;
            pr2[tid * 17 + 16] = rsg;
        }
        __syncthreads();
#pragma unroll
        for (int mi = 0; mi < 2; mi++)
#pragma unroll
            for (int ni = 0; ni < 4; ni++) {
                const int n0 = bn + wn * 32 + ni * 8 + cq;
                const float g0 = lng[n0], g1 = lng[n0 + 1];
                const float bb0 = lnb[n0], bb1 = lnb[n0 + 1];
#pragma unroll
                for (int half = 0; half < 2; half++) {
                    const int row = wm * 32 + mi * 16 + half * 8 + rq;
                    const int m = bm + row;
                    const float mu = pr[row * 17 + 16], rsg = pr2[row * 17 + 16];
                    const float v0 = acc[mi][ni][half * 2 + 0];
                    const float v1 = acc[mi][ni][half * 2 + 1];
                    if (WF) {
                        float2 o; o.x = v0; o.y = v1;
                        *(float2*)&Cf[(size_t)m * N + n0] = o;
                    }
                    unsigned hi, lo;
                    split2((v0 - mu) * rsg * g0 + bb0, (v1 - mu) * rsg * g1 + bb1, hi, lo);
                    *(unsigned*)(Ch + (size_t)m * N + n0) = hi;
                    *(unsigned*)(Cl + (size_t)m * N + n0) = lo;
                }
            }
    } else {
        float gs = 0.f, gs2 = 0.f;
#pragma unroll
        for (int mi = 0; mi < 2; mi++) {
            const int mA = bm + wm * 32 + mi * 16 + rq;
#pragma unroll
            for (int ni = 0; ni < 4; ni++) {
                const int n0 = bn + wn * 32 + ni * 8 + cq;
                const float bv0 = bias[n0], bv1 = bias[n0 + 1];
#pragma unroll
                for (int half = 0; half < 2; half++) {
                    const int m = mA + half * 8;
                    float v0 = acc[mi][ni][half * 2 + 0] + bv0;
                    float v1 = acc[mi][ni][half * 2 + 1] + bv1;
                    if (EPI == 1) {
                        v0 += R[(size_t)m * N + n0];
                        v1 += R[(size_t)m * N + n0 + 1];
                    }
                    if (EPI == 2) { v0 = fmaxf(v0, 0.f); v1 = fmaxf(v1, 0.f); }
                    if (EPI == 3) { v0 = gelu_exact(v0); v1 = gelu_exact(v1); }
                    if (WF) {
                        float2 o; o.x = v0; o.y = v1;
                        *(float2*)&Cf[(size_t)m * N + n0] = o;
                    }
                    if (WB) {
                        unsigned hi, lo;
                        split2(v0, v1, hi, lo);
                        *(unsigned*)(Ch + (size_t)m * N + n0) = hi;
                        *(unsigned*)(Cl + (size_t)m * N + n0) = lo;
                    }
                    if (GNP) { gs += v0 + v1; gs2 += v0 * v0 + v1 * v1; }
                }
            }
        }
        if (GNP) {
            float* sh  = (float*)smem;
            float* sh2 = sh + 8;
            gs = warp_sum(gs); gs2 = warp_sum(gs2);
            if (lane == 0) { sh[wid] = gs; sh2[wid] = gs2; }
            __syncthreads();
            if (tid == 0) {
                float a = 0.f, a2 = 0.f;
#pragma unroll
                for (int i = 0; i < 8; i++) { a += sh[i]; a2 += sh2[i]; }
                part[blockIdx.x * 2] = a;
                part[blockIdx.x * 2 + 1] = a2;
            }
        }
    }
}

// ------------- tiled NCHW->NHWC transpose + GN stage-1 partials --------------
__global__ void t2n(const float* __restrict__ x, float* __restrict__ o,
                    float* __restrict__ part) {
    // grid (128, 8): x = hw-tile, y = n*4 + c-tile ; block (32, 8)
    __shared__ float tile[32][33];
    const int hwt = blockIdx.x;
    const int yb  = blockIdx.y;
    const int n = yb >> 2, ct = yb & 3;
    const int tx = threadIdx.x, ty = threadIdx.y;
    float s = 0.f, s2 = 0.f;
    const int hw = hwt * 32 + tx;
#pragma unroll
    for (int i = 0; i < 4; i++) {
        const int c = ct * 32 + ty + i * 8;
        float v = x[((n * CH + c) << 12) + hw];
        tile[ty + i * 8][tx] = v;
        s += v; s2 += v * v;
    }
    __syncthreads();
#pragma unroll
    for (int i = 0; i < 4; i++) {
        const int hw2 = hwt * 32 + ty + i * 8;
        const int c2  = ct * 32 + tx;
        o[(((n << 12) + hw2) << 7) + c2] = tile[tx][ty + i * 8];
    }
    __shared__ float sh[8], sh2[8];
    s = warp_sum(s); s2 = warp_sum(s2);
    if (tx == 0) { sh[ty] = s; sh2[ty] = s2; }
    __syncthreads();
    if (tx == 0 && ty == 0) {
        float a = 0.f, a2 = 0.f;
#pragma unroll
        for (int i = 0; i < 8; i++) { a += sh[i]; a2 += sh2[i]; }
        const int b = yb * 128 + hwt;
        part[b * 2] = a; part[b * 2 + 1] = a2;
    }
}

// --------------- GN stage-2: reduce cnt partials per sample ------------------
__global__ void gn_stage2v(const float* __restrict__ part, float* __restrict__ stats,
                           int cnt) {
    const int n = blockIdx.x;
    float s = 0.f, s2 = 0.f;
    for (int i = threadIdx.x; i < cnt; i += 256) {
        s  += part[(n * cnt + i) * 2];
        s2 += part[(n * cnt + i) * 2 + 1];
    }
    __shared__ float sh[8], sh2[8];
    s = warp_sum(s); s2 = warp_sum(s2);
    if ((threadIdx.x & 31) == 0) { sh[threadIdx.x >> 5] = s; sh2[threadIdx.x >> 5] = s2; }
    __syncthreads();
    if (threadIdx.x == 0) {
        float a = 0.f, a2 = 0.f;
#pragma unroll
        for (int i = 0; i < 8; i++) { a += sh[i]; a2 += sh2[i]; }
        const float mu  = a * (1.f / 524288.f);
        const float var = a2 * (1.f / 524288.f) - mu * mu;
        stats[n * 2]     = mu;
        stats[n * 2 + 1] = rsqrtf(var + 1e-5f);
    }
}

// ----------------------- merged weight split/pack ---------------------------
__global__ void wsplit_all(const float* __restrict__ qw, const float* __restrict__ pw,
                           const float* __restrict__ f1, const float* __restrict__ f2,
                           const float* __restrict__ bw,
                           bf16* qh, bf16* ql, bf16* ph, bf16* pl,
                           bf16* f1h, bf16* f1l, bf16* f2h, bf16* f2l,
                           bf16* wh, bf16* wl) {
    int j = blockIdx.x * 256 + threadIdx.x;
    const float* src; bf16 *dh, *dl;
    if (j < 98304)      { src = qw; dh = qh; dl = ql; }
    else if ((j -= 98304) < 32768)  { src = pw; dh = ph; dl = pl; }
    else if ((j -= 32768) < 131072) { src = f1; dh = f1h; dl = f1l; }
    else if ((j -= 131072) < 131072){ src = f2; dh = f2h; dl = f2l; }
    else {
        j -= 131072;
        if (j >= CH * K_CONV) return;
        const int co = j / K_CONV;
        const int r  = j - co * K_CONV;
        const int p9 = r >> 7, ci = r & 127;
        unsigned short hh, ll;
        splitf(bw[co * K_CONV + ci * 9 + p9], hh, ll);
        wh[j] = __ushort_as_bfloat16(hh);
        wl[j] = __ushort_as_bfloat16(ll);
        return;
    }
    unsigned short hh, ll;
    splitf(src[j], hh, ll);
    dh[j] = __ushort_as_bfloat16(hh);
    dl[j] = __ushort_as_bfloat16(ll);
}

// ----------------------- 7x7 neighborhood attention -------------------------
__global__ void __launch_bounds__(256)
na_attn2(const float* __restrict__ qkv, const float* __restrict__ rpb,
         bf16* __restrict__ oh, bf16* __restrict__ ol) {
    int tok  = (blockIdx.x * 256 + threadIdx.x) >> 5;
    int lane = threadIdx.x & 31;
    int head = lane >> 3;
    int dc   = lane & 7;
    int n = tok >> 12, h = (tok >> 6) & 63, w = tok & 63;
    int i0 = min(max(h - 3, 0), 57);
    int j0 = min(max(w - 3, 0), 57);

    const float* base = qkv + ((size_t)(n << 12)) * 384;
    const int co = head * 32 + dc * 4;

    float4 q = *(const float4*)(qkv + (size_t)tok * 384 + co);
    const float sc = 0.17677669529663687f;
    q.x *= sc; q.y *= sc; q.z *= sc; q.w *= sc;

    const float* rp = rpb + head * 169 + (i0 - h + 6) * 13 + (j0 - w + 6);

    float s[7] = {-1e30f, -1e30f, -1e30f, -1e30f, -1e30f, -1e30f, -1e30f};
    float m = -1e30f;
#pragma unroll
    for (int jj = 0; jj < 49; jj++) {
        const int r = jj / 7, cd = jj % 7;
        const int kt = ((i0 + r) << 6) + (j0 + cd);
        float4 kv = *(const float4*)(base + (size_t)kt * 384 + 128 + co);
        float p = q.x * kv.x + q.y * kv.y + q.z * kv.z + q.w * kv.w;
        p += __shfl_xor_sync(0xffffffffu, p, 4);
        p += __shfl_xor_sync(0xffffffffu, p, 2);
        p += __shfl_xor_sync(0xffffffffu, p, 1);
        p += rp[r * 13 + cd];
        m = fmaxf(m, p);
        if (dc == (jj & 7)) s[jj >> 3] = p;
    }

    float e[7];
    float z = 0.f;
#pragma unroll
    for (int i = 0; i < 7; i++) { e[i] = __expf(s[i] - m); z += e[i]; }
    z += __shfl_xor_sync(0xffffffffu, z, 4);
    z += __shfl_xor_sync(0xffffffffu, z, 2);
    z += __shfl_xor_sync(0xffffffffu, z, 1);
    const float inv = 1.f / z;

    float4 acc = make_float4(0.f, 0.f, 0.f, 0.f);
#pragma unroll
    for (int jj = 0; jj < 49; jj++) {
        const int r = jj / 7, cd = jj % 7;
        const int kt = ((i0 + r) << 6) + (j0 + cd);
        float wgt = __shfl_sync(0xffffffffu, e[jj >> 3], (lane & 24) | (jj & 7));
        float4 v = *(const float4*)(base + (size_t)kt * 384 + 256 + co);
        acc.x += wgt * v.x; acc.y += wgt * v.y;
        acc.z += wgt * v.z; acc.w += wgt * v.w;
    }
    uint2 hi, lo;
    split4(acc.x * inv, acc.y * inv, acc.z * inv, acc.w * inv, hi, lo);
    ((uint2*)oh)[tok * 32 + (co >> 2)] = hi;
    ((uint2*)ol)[tok * 32 + (co >> 2)] = lo;
}

// ------------------- fused tail: c1 -> relu -> c2 + pool ---------------------
#define TAIL_SMEM 74240
__global__ void __launch_bounds__(256)
tail_k(const float* __restrict__ conv,
       const float* __restrict__ w1, const float* __restrict__ b1,
       const float* __restrict__ w2, const float* __restrict__ b2,
       float* __restrict__ y2, float* __restrict__ pp) {
    extern __shared__ float sm[];
    float* w1s = sm;                    // [32][128]
    float* w2s = sm + 4096;             // [128][32]
    float* y1s = sm + 8192;             // [64][33]
    float* y2s = sm + 8192 + 64 * 33;   // [64][129]
    const int tid = threadIdx.x;
    for (int i = tid; i < 4096; i += 256) { w1s[i] = w1[i]; w2s[i] = w2[i]; }
    __syncthreads();
    const int t0 = blockIdx.x * 64;
    const int tl = tid >> 2, q = tid & 3;

    float s[8];
#pragma unroll
    for (int d = 0; d < 8; d++) s[d] = b1[q * 8 + d];
    const float4* crow = (const float4*)(conv + (size_t)(t0 + tl) * 128);
#pragma unroll 8
    for (int c4i = 0; c4i < 32; c4i++) {
        const float4 cv = crow[c4i];
#pragma unroll
        for (int d = 0; d < 8; d++) {
            const float4 wv = *(const float4*)&w1s[(q * 8 + d) * 128 + c4i * 4];
            s[d] += cv.x * wv.x + cv.y * wv.y + cv.z * wv.z + cv.w * wv.w;
        }
    }
#pragma unroll
    for (int d = 0; d < 8; d++) y1s[tl * 33 + q * 8 + d] = fmaxf(s[d], 0.f);
    __syncthreads();

    float yv[32];
#pragma unroll 4
    for (int d = 0; d < 32; d++) {
        float a = b2[q * 32 + d];
#pragma unroll
        for (int j = 0; j < 32; j++) a += y1s[tl * 33 + j] * w2s[(q * 32 + d) * 32 + j];
        yv[d] = a;
    }
#pragma unroll
    for (int d = 0; d < 32; d++) y2s[tl * 129 + q * 32 + d] = yv[d];
    float* orow = y2 + (size_t)(t0 + tl) * 128 + q * 32;
#pragma unroll
    for (int d = 0; d < 32; d += 4)
        *(float4*)(orow + d) = make_float4(yv[d], yv[d+1], yv[d+2], yv[d+3]);
    __syncthreads();

    if (tid < 128) {
        float ps = 0.f;
#pragma unroll 8
        for (int t = 0; t < 64; t++) ps += y2s[t * 129 + tid];
        pp[blockIdx.x * 128 + tid] = ps;
    }
}

__global__ void pool2(const float* __restrict__ pp, float* __restrict__ p) {
    int n = blockIdx.x, c = threadIdx.x;
    float s = 0.f;
    for (int b = 0; b < 64; b++) s += pp[(n * 64 + b) * 128 + c];
    p[n * CH + c] = s * (1.f / 4096.f);
}

__global__ void ca_kernel(const float* __restrict__ p,
                          const float* __restrict__ w1, const float* __restrict__ b1,
                          const float* __restrict__ w2, const float* __restrict__ b2,
                          float* __restrict__ s) {
    int n = blockIdx.x, c = threadIdx.x;
    __shared__ float sp[128], sh[7];
    sp[c] = p[n * CH + c];
    __syncthreads();
    if (c < 7) {
        float a = b1[c];
        for (int i = 0; i < 128; i++) a += w1[c * 128 + i] * sp[i];
        sh[c] = fmaxf(a, 0.f);
    }
    __syncthreads();
    float a = b2[c];
    for (int j = 0; j < 7; j++) a += w2[c * 7 + j] * sh[j];
    s[n * CH + c] = 1.f / (1.f + __expf(-a));
}

__global__ void final_k(const float* __restrict__ y2, const float* __restrict__ s,
                        const float* __restrict__ x, float* __restrict__ out) {
    int idx = blockIdx.x * blockDim.x + threadIdx.x;   // NCHW index
    if (idx >= ELEMS) return;
    int hw = idx & 4095;
    int c  = (idx >> 12) & 127;
    int n  = idx >> 19;
    out[idx] = y2[(((size_t)(n << 12) + hw) << 7) + c] * s[n * CH + c] + x[idx];
}

// ------------------------------- launcher -----------------------------------
template <typename T>
static T* symf(const void* s) {
    void* p = nullptr;
    cudaGetSymbolAddress(&p, s);
    return (T*)p;
}

extern "C" void kernel_launch(void* const* d_in, const int* in_sizes, int n_in,
                              void* d_out, int out_size) {
    const float* x      = (const float*)d_in[0];
    const float* gn_g   = (const float*)d_in[1];
    const float* gn_b   = (const float*)d_in[2];
    const float* qkv_w  = (const float*)d_in[3];
    const float* qkv_b  = (const float*)d_in[4];
    const float* proj_w = (const float*)d_in[5];
    const float* proj_b = (const float*)d_in[6];
    const float* rpb    = (const float*)d_in[7];
    const float* ln_g   = (const float*)d_in[8];
    const float* ln_b   = (const float*)d_in[9];
    const float* fc1_w  = (const float*)d_in[10];
    const float* fc1_b  = (const float*)d_in[11];
    const float* fc2_w  = (const float*)d_in[12];
    const float* fc2_b  = (const float*)d_in[13];
    const float* bconv_w= (const float*)d_in[14];
    const float* bconv_b= (const float*)d_in[15];
    const float* c1_w   = (const float*)d_in[16];
    const float* c1_b   = (const float*)d_in[17];
    const float* c2_w   = (const float*)d_in[18];
    const float* c2_b   = (const float*)d_in[19];
    const float* ca1_w  = (const float*)d_in[20];
    const float* ca1_b  = (const float*)d_in[21];
    const float* ca2_w  = (const float*)d_in[22];
    const float* ca2_b  = (const float*)d_in[23];

    float* res  = symf<float>(g_res);
    float* qkv  = symf<float>(g_qkv);
    float* t    = symf<float>(g_t);
    float* conv = symf<float>(g_conv);
    float* y2   = symf<float>(g_y2);
    float* part = symf<float>(g_part);
    float* stat = symf<float>(g_stat);
    float* pp   = symf<float>(g_pp);
    float* p    = symf<float>(g_p);
    float* s    = symf<float>(g_s);

    bf16* a_h  = symf<bf16>(g_a_h);   bf16* a_l  = symf<bf16>(g_a_l);
    bf16* ln_h = symf<bf16>(g_ln_h);  bf16* ln_l = symf<bf16>(g_ln_l);
    bf16* hh_h = symf<bf16>(g_hh_h);  bf16* hh_l = symf<bf16>(g_hh_l);
    bf16* res_h= symf<bf16>(g_res_h); bf16* res_l= symf<bf16>(g_res_l);
    bf16* qw_h = symf<bf16>(g_qw_h);  bf16* qw_l = symf<bf16>(g_qw_l);
    bf16* pw_h = symf<bf16>(g_pw_h);  bf16* pw_l = symf<bf16>(g_pw_l);
    bf16* f1_h = symf<bf16>(g_f1_h);  bf16* f1_l = symf<bf16>(g_f1_l);
    bf16* f2_h = symf<bf16>(g_f2_h);  bf16* f2_l = symf<bf16>(g_f2_l);
    bf16* wp_h = symf<bf16>(g_wp_h);  bf16* wp_l = symf<bf16>(g_wp_l);

    // tgemm variants:        EPI  CONV   WB     WF     GNA    LNE    GNP
    auto* k_qkv  = tgemm<0, false, false, true,  true,  false, false>;
    auto* k_proj = tgemm<1, false, false, true,  false, true,  false>;
    auto* k_fc1  = tgemm<3, false, true,  false, false, false, false>;
    auto* k_fc2  = tgemm<1, false, true,  true,  false, false, true >;
    auto* k_conv = tgemm<0, true,  false, true,  false, false, false>;
    cudaFuncSetAttribute(k_qkv,  cudaFuncAttributeMaxDynamicSharedMemorySize, TG_SMEM);
    cudaFuncSetAttribute(k_proj, cudaFuncAttributeMaxDynamicSharedMemorySize, TG_SMEM);
    cudaFuncSetAttribute(k_fc1,  cudaFuncAttributeMaxDynamicSharedMemorySize, TG_SMEM);
    cudaFuncSetAttribute(k_fc2,  cudaFuncAttributeMaxDynamicSharedMemorySize, TG_SMEM);
    cudaFuncSetAttribute(k_conv, cudaFuncAttributeMaxDynamicSharedMemorySize, TG_SMEM);
    cudaFuncSetAttribute(tail_k, cudaFuncAttributeMaxDynamicSharedMemorySize, TAIL_SMEM);

    // transpose + GN(l=0) stage-1 partials
    t2n<<<dim3(128, 8), dim3(32, 8)>>>(x, res, part);

    wsplit_all<<<(98304 + 32768 + 131072 + 131072 + CH * K_CONV + 255) / 256, 256>>>(
        qkv_w, proj_w, fc1_w, fc2_w, bconv_w,
        qw_h, qw_l, pw_h, pw_l, f1_h, f1_l, f2_h, f2_l, wp_h, wp_l);

    for (int l = 0; l < 2; l++) {
        gn_stage2v<<<2, 256>>>(part, stat, l == 0 ? 512 : 64);

        // qkv = (GN(res) @ Wq^T + b) with GN fused into A loader
        k_qkv<<<dim3(128, 3), 256, TG_SMEM>>>(
            nullptr, nullptr, res, qw_h + l*49152, qw_l + l*49152,
            qkv_b + l*384, nullptr, qkv, nullptr, nullptr,
            stat, gn_g + l*128, gn_b + l*128, nullptr, nullptr, nullptr, 384, 128);

        na_attn2<<<1024, 256>>>(qkv, rpb + l*4*169, a_h, a_l);

        // t = attn@Wp + b + res ; LN(t) -> ln splits (fused epilogue)
        k_proj<<<dim3(128, 1), 256, TG_SMEM>>>(
            a_h, a_l, nullptr, pw_h + l*16384, pw_l + l*16384,
            proj_b + l*128, res, t, ln_h, ln_l,
            nullptr, nullptr, nullptr, ln_g + l*128, ln_b + l*128, nullptr, 128, 128);

        // h = gelu(ln @ W1^T + b) -> bf16 splits only
        k_fc1<<<dim3(128, 4), 256, TG_SMEM>>>(
            ln_h, ln_l, nullptr, f1_h + l*65536, f1_l + l*65536,
            fc1_b + l*512, nullptr, nullptr, hh_h, hh_l,
            nullptr, nullptr, nullptr, nullptr, nullptr, nullptr, 512, 128);

        // res = h @ W2^T + b + t ; also GN stage-1 partials for next layer
        k_fc2<<<dim3(128, 1), 256, TG_SMEM>>>(
            hh_h, hh_l, nullptr, f2_h + l*65536, f2_l + l*65536,
            fc2_b + l*128, t, res, res_h, res_l,
            nullptr, nullptr, nullptr, nullptr, nullptr, part, 128, 512);
    }

    // conv3x3 via fused im2col gather on bf16 split of res
    k_conv<<<dim3(128, 1), 256, TG_SMEM>>>(
        res_h, res_l, nullptr, wp_h, wp_l, bconv_b, nullptr, conv, nullptr, nullptr,
        nullptr, nullptr, nullptr, nullptr, nullptr, nullptr, 128, K_CONV);

    tail_k<<<128, 256, TAIL_SMEM>>>(conv, c1_w, c1_b, c2_w, c2_b, y2, pp);
    pool2<<<2, 128>>>(pp, p);
    ca_kernel<<<2, 128>>>(p, ca1_w, ca1_b, ca2_w, ca2_b, s);
    final_k<<<ELEMS / 256, 256>>>(y2, s, x, (float*)d_out);
}